// round 3
// baseline (speedup 1.0000x reference)
#include <cuda_runtime.h>
#include <cuda_bf16.h>
#include <cstdint>

#define MAXN 100000
#define MAXE 3200000
#define CIN 128
#define H1 50
#define H1P 52   // padded stride (13 float4), col 50 = softmax-denominator marker
#define H2 40
#define H2P 44   // padded stride (11 float4), col 40 = marker
#define NEG_SLOPE 0.2f

// -------- scratch (device globals; no runtime allocation allowed) ----------
__device__ float    g_h1[(size_t)MAXN * H1P];
__device__ float    g_acc1[(size_t)MAXN * H1P];
__device__ float    g_h2[(size_t)MAXN * H2P];
__device__ float    g_acc2[(size_t)MAXN * H2P];
__device__ float    g_as1[MAXN], g_ad1[MAXN];
__device__ float    g_as2[MAXN], g_ad2[MAXN];
__device__ unsigned g_m1[MAXN], g_m2[MAXN];
__device__ int      g_src32[MAXE + MAXN];
__device__ int      g_dst32[MAXE + MAXN];
__device__ int      g_is64;   // 1 if edge_index buffer is int64, 0 if int32

// order-preserving float<->uint map for atomicMax on floats of any sign
__device__ __forceinline__ unsigned fenc(float f) {
    unsigned b = __float_as_uint(f);
    return (b & 0x80000000u) ? ~b : (b | 0x80000000u);
}
__device__ __forceinline__ float fdec(unsigned u) {
    unsigned b = (u & 0x80000000u) ? (u & 0x7FFFFFFFu) : ~u;
    return __uint_as_float(b);
}

// ---------------- dtype probe: are the first K 8-byte slots all <2^32? ------
__global__ void detect_k(const uint2* __restrict__ ei8, long long twoE) {
    __shared__ int anyHi;
    if (threadIdx.x == 0) anyHi = 0;
    __syncthreads();
    long long K = twoE < 1024 ? twoE : 1024;   // 8-byte slots valid under either dtype (2E>=1024 ints)
    for (long long i = threadIdx.x; i < K; i += blockDim.x) {
        uint2 v = ei8[i];
        if (v.y != 0u) anyHi = 1;               // int32 data: "high word" = next index, ~never 0 for all
    }
    __syncthreads();
    if (threadIdx.x == 0) g_is64 = anyHi ? 0 : 1;
}

// ---------------- normalize indices to int32 (+ append self-loops) ----------
__global__ void convert_k(const void* __restrict__ ei, long long E, int n,
                          int* __restrict__ src, int* __restrict__ dst) {
    long long i = (long long)blockIdx.x * blockDim.x + threadIdx.x;
    long long ET = E + n;
    if (i >= ET) return;
    int s, d;
    if (i < E) {
        if (g_is64) {
            const long long* p = (const long long*)ei;
            s = (int)p[i]; d = (int)p[E + i];
        } else {
            const int* p = (const int*)ei;
            s = p[i]; d = p[E + i];
        }
        if ((unsigned)s >= (unsigned)n) s = 0;   // defensive clamp
        if ((unsigned)d >= (unsigned)n) d = 0;
    } else {
        s = d = (int)(i - E);                    // implicit self-loops
    }
    src[i] = s; dst[i] = d;
}

// ---------------- GEMM1: h1 = x @ W1  (128 -> 50), + att dots ---------------
__global__ void gemm1_k(const float* __restrict__ x, const float* __restrict__ W,
                        const float* __restrict__ att_s, const float* __restrict__ att_d,
                        int n, float* __restrict__ h,
                        float* __restrict__ as_o, float* __restrict__ ad_o) {
    __shared__ float Ws[CIN * H1P];      // [k][f], stride 52
    __shared__ float xs[128 * 17];       // 128 nodes x 16 k-chunk, stride 17 (conflict-free)
    __shared__ float sa[H1], sd[H1];
    int tid = threadIdx.x;
    for (int j = tid; j < CIN * H1; j += 128) {
        int k = j / H1, f = j - k * H1;
        Ws[k * H1P + f] = W[j];
    }
    if (tid < H1) { sa[tid] = att_s[tid]; sd[tid] = att_d[tid]; }

    int node = blockIdx.x * 128 + tid;
    float acc[H1];
#pragma unroll
    for (int f = 0; f < H1; f++) acc[f] = 0.f;

    const float4* x4 = (const float4*)x;
    for (int k0 = 0; k0 < CIN; k0 += 16) {
        __syncthreads();
#pragma unroll
        for (int j = tid; j < 512; j += 128) {
            int nd = j >> 2, c = j & 3;
            int gn = blockIdx.x * 128 + nd;
            float4 v = make_float4(0.f, 0.f, 0.f, 0.f);
            if (gn < n) v = x4[(size_t)gn * (CIN / 4) + (k0 >> 2) + c];
            float* p = &xs[nd * 17 + c * 4];
            p[0] = v.x; p[1] = v.y; p[2] = v.z; p[3] = v.w;
        }
        __syncthreads();
#pragma unroll
        for (int kk = 0; kk < 16; kk++) {
            float xv = xs[tid * 17 + kk];
#pragma unroll
            for (int f = 0; f < H1; f++) acc[f] += xv * Ws[(k0 + kk) * H1P + f];
        }
    }
    if (node < n) {
        float s = 0.f, d = 0.f;
        float* hr = h + (size_t)node * H1P;
#pragma unroll
        for (int f = 0; f < H1; f++) {
            s += acc[f] * sa[f];
            d += acc[f] * sd[f];
            hr[f] = acc[f];
        }
        hr[H1] = 1.0f;      // marker column -> accumulates softmax denominator z
        hr[H1 + 1] = 0.f;
        as_o[node] = s; ad_o[node] = d;
    }
}

// ---------------- GEMM2: h2 = relu_out1 @ W2  (50 -> 40), + att dots --------
__global__ void gemm2_k(const float* __restrict__ hin /*stride H1P*/, const float* __restrict__ W,
                        const float* __restrict__ att_s, const float* __restrict__ att_d,
                        int n, float* __restrict__ h,
                        float* __restrict__ as_o, float* __restrict__ ad_o) {
    __shared__ float Ws[H1 * H2P];
    __shared__ float xs[128 * 53];      // stride 53 -> conflict-free
    __shared__ float sa[H2], sd[H2];
    int tid = threadIdx.x;
    for (int j = tid; j < H1 * H2; j += 128) {
        int k = j / H2, f = j - k * H2;
        Ws[k * H2P + f] = W[j];
    }
    if (tid < H2) { sa[tid] = att_s[tid]; sd[tid] = att_d[tid]; }

    const float4* hin4 = (const float4*)hin;
#pragma unroll
    for (int j = tid; j < 128 * 13; j += 128) {
        int nd = j / 13, q = j - nd * 13;
        int gn = blockIdx.x * 128 + nd;
        float4 v = make_float4(0.f, 0.f, 0.f, 0.f);
        if (gn < n) v = hin4[(size_t)gn * 13 + q];
        float* p = &xs[nd * 53 + q * 4];
        p[0] = v.x; p[1] = v.y; p[2] = v.z; p[3] = v.w;
    }
    __syncthreads();

    int node = blockIdx.x * 128 + tid;
    float acc[H2];
#pragma unroll
    for (int f = 0; f < H2; f++) acc[f] = 0.f;
#pragma unroll 2
    for (int k = 0; k < H1; k++) {
        float xv = xs[tid * 53 + k];
#pragma unroll
        for (int f = 0; f < H2; f++) acc[f] += xv * Ws[k * H2P + f];
    }
    if (node < n) {
        float s = 0.f, d = 0.f;
        float* hr = h + (size_t)node * H2P;
#pragma unroll
        for (int f = 0; f < H2; f++) {
            s += acc[f] * sa[f];
            d += acc[f] * sd[f];
            hr[f] = acc[f];
        }
        hr[H2] = 1.0f;
        hr[H2 + 1] = 0.f; hr[H2 + 2] = 0.f; hr[H2 + 3] = 0.f;
        as_o[node] = s; ad_o[node] = d;
    }
}

// ---------------- edge pass A: segment max over dst --------------------------
__global__ void edge_max_k(const int* __restrict__ src_a, const int* __restrict__ dst_a,
                           long long ET,
                           const float* __restrict__ as, const float* __restrict__ ad,
                           unsigned* __restrict__ m) {
    long long i = (long long)blockIdx.x * blockDim.x + threadIdx.x;
    if (i >= ET) return;
    int s = src_a[i], d = dst_a[i];
    float e = as[s] + ad[d];
    e = e > 0.f ? e : NEG_SLOPE * e;
    atomicMax(m + d, fenc(e));
}

// ---------------- edge pass B: acc[dst] += w * h[src] (v4 global reductions) -
template <int NV4>
__global__ void edge_acc_k(const int* __restrict__ src_a, const int* __restrict__ dst_a,
                           long long ET,
                           const float* __restrict__ as, const float* __restrict__ ad,
                           const unsigned* __restrict__ m,
                           const float* __restrict__ h, float* __restrict__ acc) {
    long long i = (long long)blockIdx.x * blockDim.x + threadIdx.x;
    if (i >= ET) return;
    int s = src_a[i], d = dst_a[i];
    float e = as[s] + ad[d];
    e = e > 0.f ? e : NEG_SLOPE * e;
    float w = __expf(e - fdec(m[d]));
    const float4* hr = (const float4*)(h + (size_t)s * (NV4 * 4));
    float* ar = acc + (size_t)d * (NV4 * 4);
#pragma unroll
    for (int j = 0; j < NV4; j++) {
        float4 v = __ldg(hr + j);
        asm volatile("red.global.add.v4.f32 [%0], {%1,%2,%3,%4};"
                     :: "l"(ar + j * 4),
                        "f"(w * v.x), "f"(w * v.y), "f"(w * v.z), "f"(w * v.w)
                     : "memory");
    }
}

// ---------------- finalize: out = relu(acc / z + bias) -----------------------
__global__ void finalize_k(const float* __restrict__ acc, const float* __restrict__ bias,
                           int n, int F, int STRIDE, float* __restrict__ out, int outStride) {
    long long t = (long long)blockIdx.x * blockDim.x + threadIdx.x;
    if (t >= (long long)n * F) return;
    int node = (int)(t / F);
    int f = (int)(t - (long long)node * F);
    float z = acc[(size_t)node * STRIDE + F];   // marker column
    float v = acc[(size_t)node * STRIDE + f] / z + bias[f];
    out[(size_t)node * outStride + f] = v > 0.f ? v : 0.f;
}

// ---------------- edge_index tail (cast to float, dtype-aware) ---------------
__global__ void ei_cast_k(const void* __restrict__ ei, float* __restrict__ o, long long cnt) {
    long long i = (long long)blockIdx.x * blockDim.x + threadIdx.x;
    if (i >= cnt) return;
    if (g_is64) o[i] = (float)((const long long*)ei)[i];
    else        o[i] = (float)((const int*)ei)[i];
}

extern "C" void kernel_launch(void* const* d_in, const int* in_sizes, int n_in,
                              void* d_out, int out_size) {
    const float* x    = (const float*)d_in[0];
    const void*  ei   = d_in[1];
    const float* W1   = (const float*)d_in[2];
    const float* as1w = (const float*)d_in[3];
    const float* ad1w = (const float*)d_in[4];
    const float* b1   = (const float*)d_in[5];
    const float* W2   = (const float*)d_in[6];
    const float* as2w = (const float*)d_in[7];
    const float* ad2w = (const float*)d_in[8];
    const float* b2   = (const float*)d_in[9];

    int       n  = in_sizes[0] / CIN;
    long long E  = (long long)in_sizes[1] / 2;
    long long ET = E + n;

    float *h1, *acc1, *h2, *acc2, *pas1, *pad1, *pas2, *pad2;
    unsigned *m1, *m2;
    int *srcA, *dstA;
    cudaGetSymbolAddress((void**)&h1,   g_h1);
    cudaGetSymbolAddress((void**)&acc1, g_acc1);
    cudaGetSymbolAddress((void**)&h2,   g_h2);
    cudaGetSymbolAddress((void**)&acc2, g_acc2);
    cudaGetSymbolAddress((void**)&pas1, g_as1);
    cudaGetSymbolAddress((void**)&pad1, g_ad1);
    cudaGetSymbolAddress((void**)&pas2, g_as2);
    cudaGetSymbolAddress((void**)&pad2, g_ad2);
    cudaGetSymbolAddress((void**)&m1,   g_m1);
    cudaGetSymbolAddress((void**)&m2,   g_m2);
    cudaGetSymbolAddress((void**)&srcA, g_src32);
    cudaGetSymbolAddress((void**)&dstA, g_dst32);

    int nodeBlocks = (n + 127) / 128;
    int edgeBlocks = (int)((ET + 255) / 256);

    // ---------------- index normalization ----------------
    detect_k<<<1, 256>>>((const uint2*)ei, 2 * E);
    convert_k<<<edgeBlocks, 256>>>(ei, E, n, srcA, dstA);

    // ---------------- layer 1 ----------------
    cudaMemsetAsync(m1, 0, (size_t)n * sizeof(unsigned));   // fenc of any finite float > small positives; 0 is a safe floor
    cudaMemsetAsync(acc1, 0, (size_t)n * H1P * sizeof(float));
    gemm1_k<<<nodeBlocks, 128>>>(x, W1, as1w, ad1w, n, h1, pas1, pad1);
    edge_max_k<<<edgeBlocks, 256>>>(srcA, dstA, ET, pas1, pad1, m1);
    edge_acc_k<13><<<edgeBlocks, 256>>>(srcA, dstA, ET, pas1, pad1, m1, h1, acc1);
    {
        long long tot = (long long)n * H1;
        finalize_k<<<(int)((tot + 255) / 256), 256>>>(acc1, b1, n, H1, H1P, acc1, H1P); // in-place relu(acc/z)
    }

    // ---------------- layer 2 ----------------
    cudaMemsetAsync(m2, 0, (size_t)n * sizeof(unsigned));
    cudaMemsetAsync(acc2, 0, (size_t)n * H2P * sizeof(float));
    gemm2_k<<<nodeBlocks, 128>>>(acc1, W2, as2w, ad2w, n, h2, pas2, pad2);
    edge_max_k<<<edgeBlocks, 256>>>(srcA, dstA, ET, pas2, pad2, m2);
    edge_acc_k<11><<<edgeBlocks, 256>>>(srcA, dstA, ET, pas2, pad2, m2, h2, acc2);
    {
        long long tot = (long long)n * H2;
        finalize_k<<<(int)((tot + 255) / 256), 256>>>(acc2, b2, n, H2, H2P, (float*)d_out, H2);
    }

    // ---------------- optional edge_index passthrough tail ----------------
    long long nh2 = (long long)n * H2;
    long long tail = (long long)out_size - nh2;
    if (tail == 2 * E) {
        ei_cast_k<<<(int)((2 * E + 255) / 256), 256>>>(ei, (float*)d_out + nh2, 2 * E);
    } else if (tail == 4 * E) {
        cudaMemcpyAsync((char*)d_out + nh2 * sizeof(float), ei,
                        (size_t)(2 * E) * sizeof(long long), cudaMemcpyDeviceToDevice);
    }
}

// round 4
// speedup vs baseline: 1.4500x; 1.4500x over previous
#include <cuda_runtime.h>
#include <cuda_bf16.h>
#include <cstdint>

#define MAXN 100000
#define MAXE 3200000
#define CIN 128
#define H1 50
#define H1P 52   // padded row stride (13 float4)
#define H2 40
#define H2P 44
#define NEG_SLOPE 0.2f

// -------- scratch (device globals; no runtime allocation allowed) ----------
__device__ float g_h1[(size_t)MAXN * H1P];     // gemm1 output (pre-activation h)
__device__ float g_ho1[(size_t)MAXN * H1P];    // agg1 output = relu(GAT layer1) -> gemm2 input
__device__ float g_h2[(size_t)MAXN * H2P];     // gemm2 output
__device__ float g_as1[MAXN], g_ad1[MAXN];
__device__ float g_as2[MAXN], g_ad2[MAXN];
__device__ int   g_deg[MAXN];
__device__ int   g_off[MAXN + 1];
__device__ int   g_cur[MAXN];
__device__ int   g_csr[MAXE + MAXN];           // src indices grouped by dst
__device__ int   g_is64;                       // edge_index dtype flag

// ---------------- dtype probe ----------------
__global__ void detect_k(const uint2* __restrict__ ei8, long long twoE) {
    __shared__ int anyHi;
    if (threadIdx.x == 0) anyHi = 0;
    __syncthreads();
    long long K = twoE < 1024 ? twoE : 1024;
    for (long long i = threadIdx.x; i < K; i += blockDim.x) {
        uint2 v = ei8[i];
        if (v.y != 0u) anyHi = 1;   // int32 data: high half is the next index, ~never all-zero
    }
    __syncthreads();
    if (threadIdx.x == 0) g_is64 = anyHi ? 0 : 1;
}

// ---------------- CSR build ----------------
__global__ void deginit_k(int* __restrict__ deg, int n) {
    int i = blockIdx.x * blockDim.x + threadIdx.x;
    if (i < n) deg[i] = 1;                      // self-loop
}

__global__ void count_k(const void* __restrict__ ei, long long E, int n, int* __restrict__ deg) {
    long long i = (long long)blockIdx.x * blockDim.x + threadIdx.x;
    if (i >= E) return;
    int d;
    if (g_is64) d = (int)((const long long*)ei)[E + i];
    else        d = ((const int*)ei)[E + i];
    if ((unsigned)d >= (unsigned)n) d = 0;
    atomicAdd(deg + d, 1);
}

__global__ void scan_k(const int* __restrict__ deg, int* __restrict__ off,
                       int* __restrict__ cur, int n) {
    __shared__ int ssum[1024];
    int t = threadIdx.x;
    int c = (n + 1023) >> 10;
    int b = t * c, e = b + c; if (e > n) e = n; if (b > n) b = n;
    int s = 0;
    for (int i = b; i < e; i++) s += deg[i];
    ssum[t] = s;
    __syncthreads();
#pragma unroll
    for (int d = 1; d < 1024; d <<= 1) {
        int v = (t >= d) ? ssum[t - d] : 0;
        __syncthreads();
        ssum[t] += v;
        __syncthreads();
    }
    int run = t ? ssum[t - 1] : 0;
    for (int i = b; i < e; i++) { off[i] = run; cur[i] = run; run += deg[i]; }
    if (t == 1023) off[n] = ssum[1023];
}

__global__ void scatter_k(const void* __restrict__ ei, long long E, int n,
                          int* __restrict__ cur, int* __restrict__ csr) {
    long long i = (long long)blockIdx.x * blockDim.x + threadIdx.x;
    long long ET = E + n;
    if (i >= ET) return;
    int s, d;
    if (i < E) {
        if (g_is64) {
            const long long* p = (const long long*)ei;
            s = (int)p[i]; d = (int)p[E + i];
        } else {
            const int* p = (const int*)ei;
            s = p[i]; d = p[E + i];
        }
        if ((unsigned)s >= (unsigned)n) s = 0;
        if ((unsigned)d >= (unsigned)n) d = 0;
    } else {
        s = d = (int)(i - E);
    }
    int pos = atomicAdd(cur + d, 1);
    csr[pos] = s;
}

// ---------------- GEMM1: h1 = x @ W1  (128 -> 50), + att dots ---------------
__global__ void gemm1_k(const float* __restrict__ x, const float* __restrict__ W,
                        const float* __restrict__ att_s, const float* __restrict__ att_d,
                        int n, float* __restrict__ h,
                        float* __restrict__ as_o, float* __restrict__ ad_o) {
    __shared__ float Ws[CIN * H1P];
    __shared__ float xs[128 * 17];
    __shared__ float sa[H1], sd[H1];
    int tid = threadIdx.x;
    for (int j = tid; j < CIN * H1; j += 128) {
        int k = j / H1, f = j - k * H1;
        Ws[k * H1P + f] = W[j];
    }
    if (tid < H1) { sa[tid] = att_s[tid]; sd[tid] = att_d[tid]; }

    int node = blockIdx.x * 128 + tid;
    float acc[H1];
#pragma unroll
    for (int f = 0; f < H1; f++) acc[f] = 0.f;

    const float4* x4 = (const float4*)x;
    for (int k0 = 0; k0 < CIN; k0 += 16) {
        __syncthreads();
#pragma unroll
        for (int j = tid; j < 512; j += 128) {
            int nd = j >> 2, c = j & 3;
            int gn = blockIdx.x * 128 + nd;
            float4 v = make_float4(0.f, 0.f, 0.f, 0.f);
            if (gn < n) v = x4[(size_t)gn * (CIN / 4) + (k0 >> 2) + c];
            float* p = &xs[nd * 17 + c * 4];
            p[0] = v.x; p[1] = v.y; p[2] = v.z; p[3] = v.w;
        }
        __syncthreads();
#pragma unroll
        for (int kk = 0; kk < 16; kk++) {
            float xv = xs[tid * 17 + kk];
#pragma unroll
            for (int f = 0; f < H1; f++) acc[f] += xv * Ws[(k0 + kk) * H1P + f];
        }
    }
    if (node < n) {
        float s = 0.f, d = 0.f;
        float* hr = h + (size_t)node * H1P;
#pragma unroll
        for (int f = 0; f < H1; f++) {
            s += acc[f] * sa[f];
            d += acc[f] * sd[f];
            hr[f] = acc[f];
        }
        as_o[node] = s; ad_o[node] = d;
    }
}

// ---------------- GEMM2: h2 = ho1 @ W2  (50 -> 40), + att dots --------------
__global__ void gemm2_k(const float* __restrict__ hin /*stride H1P*/, const float* __restrict__ W,
                        const float* __restrict__ att_s, const float* __restrict__ att_d,
                        int n, float* __restrict__ h,
                        float* __restrict__ as_o, float* __restrict__ ad_o) {
    __shared__ float Ws[H1 * H2P];
    __shared__ float xs[128 * 53];
    __shared__ float sa[H2], sd[H2];
    int tid = threadIdx.x;
    for (int j = tid; j < H1 * H2; j += 128) {
        int k = j / H2, f = j - k * H2;
        Ws[k * H2P + f] = W[j];
    }
    if (tid < H2) { sa[tid] = att_s[tid]; sd[tid] = att_d[tid]; }

    const float4* hin4 = (const float4*)hin;
#pragma unroll
    for (int j = tid; j < 128 * 13; j += 128) {
        int nd = j / 13, q = j - nd * 13;
        int gn = blockIdx.x * 128 + nd;
        float4 v = make_float4(0.f, 0.f, 0.f, 0.f);
        if (gn < n) v = hin4[(size_t)gn * 13 + q];
        float* p = &xs[nd * 53 + q * 4];
        p[0] = v.x; p[1] = v.y; p[2] = v.z; p[3] = v.w;
    }
    __syncthreads();

    int node = blockIdx.x * 128 + tid;
    float acc[H2];
#pragma unroll
    for (int f = 0; f < H2; f++) acc[f] = 0.f;
#pragma unroll 2
    for (int k = 0; k < H1; k++) {
        float xv = xs[tid * 53 + k];
#pragma unroll
        for (int f = 0; f < H2; f++) acc[f] += xv * Ws[k * H2P + f];
    }
    if (node < n) {
        float s = 0.f, d = 0.f;
        float* hr = h + (size_t)node * H2P;
#pragma unroll
        for (int f = 0; f < H2; f++) {
            s += acc[f] * sa[f];
            d += acc[f] * sd[f];
            hr[f] = acc[f];
        }
        as_o[node] = s; ad_o[node] = d;
    }
}

// ---------------- fused GAT aggregation: one warp per dst node ---------------
// out[v] = relu( (sum_e w_e * h[src_e]) / (sum_e w_e) + bias ),  w_e = exp(leaky(as[s]+ad[v]))
template <int F, int SIN, int SOUT>
__global__ void agg_k(const int* __restrict__ off, const int* __restrict__ csr,
                      const float* __restrict__ as, const float* __restrict__ ad,
                      const float* __restrict__ h, const float* __restrict__ bias,
                      int n, float* __restrict__ out) {
    int warp = (blockIdx.x * blockDim.x + threadIdx.x) >> 5;
    int lane = threadIdx.x & 31;
    if (warp >= n) return;
    constexpr int F2 = F - 32;

    int beg = __ldg(off + warp), end = __ldg(off + warp + 1);
    float adv = __ldg(ad + warp);
    float a0 = 0.f, a1 = 0.f, z = 0.f;

    int p = beg;
    for (; p + 4 <= end; p += 4) {
        int   s[4]; float w[4], v0[4], v1[4];
#pragma unroll
        for (int u = 0; u < 4; u++) s[u] = __ldg(csr + p + u);
#pragma unroll
        for (int u = 0; u < 4; u++) {
            float e = __ldg(as + s[u]) + adv;
            e = e > 0.f ? e : NEG_SLOPE * e;
            w[u] = __expf(e);
        }
#pragma unroll
        for (int u = 0; u < 4; u++) {
            const float* hr = h + (size_t)s[u] * SIN;
            v0[u] = __ldg(hr + lane);
            v1[u] = (lane < F2) ? __ldg(hr + 32 + lane) : 0.f;
        }
#pragma unroll
        for (int u = 0; u < 4; u++) {
            z  += w[u];
            a0 += w[u] * v0[u];
            a1 += w[u] * v1[u];
        }
    }
    for (; p < end; p++) {
        int s = __ldg(csr + p);
        float e = __ldg(as + s) + adv;
        e = e > 0.f ? e : NEG_SLOPE * e;
        float w = __expf(e);
        const float* hr = h + (size_t)s * SIN;
        z  += w;
        a0 += w * __ldg(hr + lane);
        a1 += (lane < F2) ? w * __ldg(hr + 32 + lane) : 0.f;
    }

    float inv = 1.f / z;                         // z >= exp(self-loop) > 0
    float* orow = out + (size_t)warp * SOUT;
    {
        float v = a0 * inv + __ldg(bias + lane);
        orow[lane] = v > 0.f ? v : 0.f;
    }
    if (lane < F2) {
        float v = a1 * inv + __ldg(bias + 32 + lane);
        orow[32 + lane] = v > 0.f ? v : 0.f;
    }
}

// ---------------- edge_index passthrough tail ---------------
__global__ void ei_cast_k(const void* __restrict__ ei, float* __restrict__ o, long long cnt) {
    long long i = (long long)blockIdx.x * blockDim.x + threadIdx.x;
    if (i >= cnt) return;
    if (g_is64) o[i] = (float)((const long long*)ei)[i];
    else        o[i] = (float)((const int*)ei)[i];
}

extern "C" void kernel_launch(void* const* d_in, const int* in_sizes, int n_in,
                              void* d_out, int out_size) {
    const float* x    = (const float*)d_in[0];
    const void*  ei   = d_in[1];
    const float* W1   = (const float*)d_in[2];
    const float* as1w = (const float*)d_in[3];
    const float* ad1w = (const float*)d_in[4];
    const float* b1   = (const float*)d_in[5];
    const float* W2   = (const float*)d_in[6];
    const float* as2w = (const float*)d_in[7];
    const float* ad2w = (const float*)d_in[8];
    const float* b2   = (const float*)d_in[9];

    int       n  = in_sizes[0] / CIN;
    long long E  = (long long)in_sizes[1] / 2;
    long long ET = E + n;

    float *h1, *ho1, *h2, *pas1, *pad1, *pas2, *pad2;
    int *deg, *off, *cur, *csr;
    cudaGetSymbolAddress((void**)&h1,  g_h1);
    cudaGetSymbolAddress((void**)&ho1, g_ho1);
    cudaGetSymbolAddress((void**)&h2,  g_h2);
    cudaGetSymbolAddress((void**)&pas1, g_as1);
    cudaGetSymbolAddress((void**)&pad1, g_ad1);
    cudaGetSymbolAddress((void**)&pas2, g_as2);
    cudaGetSymbolAddress((void**)&pad2, g_ad2);
    cudaGetSymbolAddress((void**)&deg, g_deg);
    cudaGetSymbolAddress((void**)&off, g_off);
    cudaGetSymbolAddress((void**)&cur, g_cur);
    cudaGetSymbolAddress((void**)&csr, g_csr);

    int nodeBlocks = (n + 127) / 128;
    int edgeBlocks  = (int)((E + 255) / 256);
    int etBlocks    = (int)((ET + 255) / 256);
    int aggBlocks   = (n * 32 + 255) / 256;     // 8 warps (nodes) per block

    // ---------------- CSR build (shared by both layers) ----------------
    detect_k<<<1, 256>>>((const uint2*)ei, 2 * E);
    deginit_k<<<(n + 255) / 256, 256>>>(deg, n);
    count_k<<<edgeBlocks, 256>>>(ei, E, n, deg);
    scan_k<<<1, 1024>>>(deg, off, cur, n);
    scatter_k<<<etBlocks, 256>>>(ei, E, n, cur, csr);

    // ---------------- layer 1 ----------------
    gemm1_k<<<nodeBlocks, 128>>>(x, W1, as1w, ad1w, n, h1, pas1, pad1);
    agg_k<H1, H1P, H1P><<<aggBlocks, 256>>>(off, csr, pas1, pad1, h1, b1, n, ho1);

    // ---------------- layer 2 ----------------
    gemm2_k<<<nodeBlocks, 128>>>(ho1, W2, as2w, ad2w, n, h2, pas2, pad2);
    agg_k<H2, H2P, H2><<<aggBlocks, 256>>>(off, csr, pas2, pad2, h2, b2, n, (float*)d_out);

    // ---------------- optional edge_index passthrough tail ----------------
    long long nh2 = (long long)n * H2;
    long long tail = (long long)out_size - nh2;
    if (tail == 2 * E) {
        ei_cast_k<<<(int)((2 * E + 255) / 256), 256>>>(ei, (float*)d_out + nh2, 2 * E);
    } else if (tail == 4 * E) {
        cudaMemcpyAsync((char*)d_out + nh2 * sizeof(float), ei,
                        (size_t)(2 * E) * sizeof(long long), cudaMemcpyDeviceToDevice);
    }
}

// round 5
// speedup vs baseline: 1.9204x; 1.3244x over previous
#include <cuda_runtime.h>
#include <cuda_bf16.h>
#include <cstdint>

#define MAXN 100000
#define MAXE 3200000
#define CIN 128
#define H1 50
#define H1P 52   // padded row stride (13 float4)
#define H2 40
#define H2P 44
#define NEG_SLOPE 0.2f
#define SCAN_CHUNK 1024

// -------- scratch (device globals; no runtime allocation allowed) ----------
__device__ float g_h1[(size_t)MAXN * H1P];     // gemm1 output (pre-activation h)
__device__ float g_ho1[(size_t)MAXN * H1P];    // agg1 output = relu(GAT layer1) -> gemm2 input
__device__ float g_h2[(size_t)MAXN * H2P];     // gemm2 output
__device__ float g_as1[MAXN], g_ad1[MAXN];
__device__ float g_as2[MAXN], g_ad2[MAXN];
__device__ int   g_deg[MAXN + 4];
__device__ int   g_off[MAXN + 1];
__device__ int   g_cur[MAXN];
__device__ int   g_part[1100];
__device__ int   g_csr[MAXE + MAXN];           // src indices grouped by dst
__device__ int   g_is64;                       // edge_index dtype flag

// ---------------- dtype probe ----------------
__global__ void detect_k(const uint2* __restrict__ ei8, long long twoE) {
    __shared__ int anyHi;
    if (threadIdx.x == 0) anyHi = 0;
    __syncthreads();
    long long K = twoE < 1024 ? twoE : 1024;
    for (long long i = threadIdx.x; i < K; i += blockDim.x) {
        uint2 v = ei8[i];
        if (v.y != 0u) anyHi = 1;   // int32 data: high half is the next index, ~never all-zero
    }
    __syncthreads();
    if (threadIdx.x == 0) g_is64 = anyHi ? 0 : 1;
}

// ---------------- CSR build ----------------
__global__ void deginit_k(int* __restrict__ deg, int n) {
    int i = blockIdx.x * blockDim.x + threadIdx.x;
    if (i < n) deg[i] = 1;                      // self-loop
}

__global__ void count_k(const void* __restrict__ ei, long long E, int n, int* __restrict__ deg) {
    long long i = (long long)blockIdx.x * blockDim.x + threadIdx.x;
    if (i >= E) return;
    int d;
    if (g_is64) d = (int)((const long long*)ei)[E + i];
    else        d = ((const int*)ei)[E + i];
    if ((unsigned)d >= (unsigned)n) d = 0;
    atomicAdd(deg + d, 1);
}

// phase 1: per-chunk sums (coalesced, order-free)
__global__ void blocksum_k(const int* __restrict__ deg, int* __restrict__ part, int n) {
    __shared__ int sred[256];
    int base = blockIdx.x * SCAN_CHUNK;
    int t = threadIdx.x;
    int s = 0;
#pragma unroll
    for (int j = 0; j < SCAN_CHUNK / 256; j++) {
        int i = base + j * 256 + t;
        if (i < n) s += deg[i];
    }
    sred[t] = s;
    __syncthreads();
#pragma unroll
    for (int d = 128; d > 0; d >>= 1) {
        if (t < d) sred[t] += sred[t + d];
        __syncthreads();
    }
    if (t == 0) part[blockIdx.x] = sred[0];
}

// phase 2: exclusive scan of the (<=1024) partials, single small block
__global__ void scan_partials_k(int* __restrict__ part, int B) {
    __shared__ int s[1024];
    int t = threadIdx.x;
    s[t] = (t < B) ? part[t] : 0;
    __syncthreads();
#pragma unroll
    for (int d = 1; d < 1024; d <<= 1) {
        int v = (t >= d) ? s[t - d] : 0;
        __syncthreads();
        s[t] += v;
        __syncthreads();
    }
    if (t < B) part[t] = t ? s[t - 1] : 0;      // exclusive base per chunk
}

// phase 3: per-chunk exclusive scan + chunk base -> off, cur
__global__ void write_off_k(const int* __restrict__ deg, const int* __restrict__ part,
                            int* __restrict__ off, int* __restrict__ cur,
                            int n, int total) {
    __shared__ int ts[256];
    int base = blockIdx.x * SCAN_CHUNK;
    int t = threadIdx.x;
    int i0 = base + t * 4;
    int v0 = 0, v1 = 0, v2 = 0, v3 = 0;
    if (i0 + 3 < n) {
        int4 q = *(const int4*)(deg + i0);      // g_deg padded, 16B-aligned chunks
        v0 = q.x; v1 = q.y; v2 = q.z; v3 = q.w;
    } else {
        if (i0 + 0 < n) v0 = deg[i0 + 0];
        if (i0 + 1 < n) v1 = deg[i0 + 1];
        if (i0 + 2 < n) v2 = deg[i0 + 2];
        if (i0 + 3 < n) v3 = deg[i0 + 3];
    }
    int tsum = v0 + v1 + v2 + v3;
    ts[t] = tsum;
    __syncthreads();
#pragma unroll
    for (int d = 1; d < 256; d <<= 1) {
        int v = (t >= d) ? ts[t - d] : 0;
        __syncthreads();
        ts[t] += v;
        __syncthreads();
    }
    int run = part[blockIdx.x] + (t ? ts[t - 1] : 0);
    if (i0 + 0 < n) { off[i0 + 0] = run; cur[i0 + 0] = run; run += v0; }
    if (i0 + 1 < n) { off[i0 + 1] = run; cur[i0 + 1] = run; run += v1; }
    if (i0 + 2 < n) { off[i0 + 2] = run; cur[i0 + 2] = run; run += v2; }
    if (i0 + 3 < n) { off[i0 + 3] = run; cur[i0 + 3] = run; run += v3; }
    if (blockIdx.x == 0 && t == 0) off[n] = total;
}

__global__ void scatter_k(const void* __restrict__ ei, long long E, int n,
                          int* __restrict__ cur, int* __restrict__ csr) {
    long long i = (long long)blockIdx.x * blockDim.x + threadIdx.x;
    long long ET = E + n;
    if (i >= ET) return;
    int s, d;
    if (i < E) {
        if (g_is64) {
            const long long* p = (const long long*)ei;
            s = (int)p[i]; d = (int)p[E + i];
        } else {
            const int* p = (const int*)ei;
            s = p[i]; d = p[E + i];
        }
        if ((unsigned)s >= (unsigned)n) s = 0;
        if ((unsigned)d >= (unsigned)n) d = 0;
    } else {
        s = d = (int)(i - E);
    }
    int pos = atomicAdd(cur + d, 1);
    csr[pos] = s;
}

// ---------------- GEMM1: h1 = x @ W1  (128 -> 50), + att dots ---------------
__global__ void gemm1_k(const float* __restrict__ x, const float* __restrict__ W,
                        const float* __restrict__ att_s, const float* __restrict__ att_d,
                        int n, float* __restrict__ h,
                        float* __restrict__ as_o, float* __restrict__ ad_o) {
    __shared__ float Ws[CIN * H1P];
    __shared__ float xs[128 * 17];
    __shared__ float sa[H1], sd[H1];
    int tid = threadIdx.x;
    for (int j = tid; j < CIN * H1; j += 128) {
        int k = j / H1, f = j - k * H1;
        Ws[k * H1P + f] = W[j];
    }
    if (tid < H1) { sa[tid] = att_s[tid]; sd[tid] = att_d[tid]; }

    int node = blockIdx.x * 128 + tid;
    float acc[H1];
#pragma unroll
    for (int f = 0; f < H1; f++) acc[f] = 0.f;

    const float4* x4 = (const float4*)x;
    for (int k0 = 0; k0 < CIN; k0 += 16) {
        __syncthreads();
#pragma unroll
        for (int j = tid; j < 512; j += 128) {
            int nd = j >> 2, c = j & 3;
            int gn = blockIdx.x * 128 + nd;
            float4 v = make_float4(0.f, 0.f, 0.f, 0.f);
            if (gn < n) v = x4[(size_t)gn * (CIN / 4) + (k0 >> 2) + c];
            float* p = &xs[nd * 17 + c * 4];
            p[0] = v.x; p[1] = v.y; p[2] = v.z; p[3] = v.w;
        }
        __syncthreads();
#pragma unroll
        for (int kk = 0; kk < 16; kk++) {
            float xv = xs[tid * 17 + kk];
#pragma unroll
            for (int f = 0; f < H1; f++) acc[f] += xv * Ws[(k0 + kk) * H1P + f];
        }
    }
    if (node < n) {
        float s = 0.f, d = 0.f;
        float* hr = h + (size_t)node * H1P;
#pragma unroll
        for (int f = 0; f < H1; f++) {
            s += acc[f] * sa[f];
            d += acc[f] * sd[f];
            hr[f] = acc[f];
        }
        as_o[node] = s; ad_o[node] = d;
    }
}

// ---------------- GEMM2: h2 = ho1 @ W2  (50 -> 40), + att dots --------------
__global__ void gemm2_k(const float* __restrict__ hin /*stride H1P*/, const float* __restrict__ W,
                        const float* __restrict__ att_s, const float* __restrict__ att_d,
                        int n, float* __restrict__ h,
                        float* __restrict__ as_o, float* __restrict__ ad_o) {
    __shared__ float Ws[H1 * H2P];
    __shared__ float xs[128 * 53];
    __shared__ float sa[H2], sd[H2];
    int tid = threadIdx.x;
    for (int j = tid; j < H1 * H2; j += 128) {
        int k = j / H2, f = j - k * H2;
        Ws[k * H2P + f] = W[j];
    }
    if (tid < H2) { sa[tid] = att_s[tid]; sd[tid] = att_d[tid]; }

    const float4* hin4 = (const float4*)hin;
#pragma unroll
    for (int j = tid; j < 128 * 13; j += 128) {
        int nd = j / 13, q = j - nd * 13;
        int gn = blockIdx.x * 128 + nd;
        float4 v = make_float4(0.f, 0.f, 0.f, 0.f);
        if (gn < n) v = hin4[(size_t)gn * 13 + q];
        float* p = &xs[nd * 53 + q * 4];
        p[0] = v.x; p[1] = v.y; p[2] = v.z; p[3] = v.w;
    }
    __syncthreads();

    int node = blockIdx.x * 128 + tid;
    float acc[H2];
#pragma unroll
    for (int f = 0; f < H2; f++) acc[f] = 0.f;
#pragma unroll 2
    for (int k = 0; k < H1; k++) {
        float xv = xs[tid * 53 + k];
#pragma unroll
        for (int f = 0; f < H2; f++) acc[f] += xv * Ws[k * H2P + f];
    }
    if (node < n) {
        float s = 0.f, d = 0.f;
        float* hr = h + (size_t)node * H2P;
#pragma unroll
        for (int f = 0; f < H2; f++) {
            s += acc[f] * sa[f];
            d += acc[f] * sd[f];
            hr[f] = acc[f];
        }
        as_o[node] = s; ad_o[node] = d;
    }
}

// ---------------- fused GAT aggregation: one warp per dst node ---------------
// out[v] = relu( (sum_e w_e * h[src_e]) / (sum_e w_e) + bias ),  w_e = exp(leaky(as[s]+ad[v]))
template <int F, int SIN, int SOUT>
__global__ void agg_k(const int* __restrict__ off, const int* __restrict__ csr,
                      const float* __restrict__ as, const float* __restrict__ ad,
                      const float* __restrict__ h, const float* __restrict__ bias,
                      int n, float* __restrict__ out) {
    int warp = (blockIdx.x * blockDim.x + threadIdx.x) >> 5;
    int lane = threadIdx.x & 31;
    if (warp >= n) return;
    constexpr int F2 = F - 32;

    int beg = __ldg(off + warp), end = __ldg(off + warp + 1);
    float adv = __ldg(ad + warp);
    float a0 = 0.f, a1 = 0.f, z = 0.f;

    int p = beg;
    for (; p + 4 <= end; p += 4) {
        int   s[4]; float w[4], v0[4], v1[4];
#pragma unroll
        for (int u = 0; u < 4; u++) s[u] = __ldg(csr + p + u);
#pragma unroll
        for (int u = 0; u < 4; u++) {
            float e = __ldg(as + s[u]) + adv;
            e = e > 0.f ? e : NEG_SLOPE * e;
            w[u] = __expf(e);
        }
#pragma unroll
        for (int u = 0; u < 4; u++) {
            const float* hr = h + (size_t)s[u] * SIN;
            v0[u] = __ldg(hr + lane);
            v1[u] = (lane < F2) ? __ldg(hr + 32 + lane) : 0.f;
        }
#pragma unroll
        for (int u = 0; u < 4; u++) {
            z  += w[u];
            a0 += w[u] * v0[u];
            a1 += w[u] * v1[u];
        }
    }
    for (; p < end; p++) {
        int s = __ldg(csr + p);
        float e = __ldg(as + s) + adv;
        e = e > 0.f ? e : NEG_SLOPE * e;
        float w = __expf(e);
        const float* hr = h + (size_t)s * SIN;
        z  += w;
        a0 += w * __ldg(hr + lane);
        a1 += (lane < F2) ? w * __ldg(hr + 32 + lane) : 0.f;
    }

    float inv = 1.f / z;                         // z >= exp(self-loop) > 0
    float* orow = out + (size_t)warp * SOUT;
    {
        float v = a0 * inv + __ldg(bias + lane);
        orow[lane] = v > 0.f ? v : 0.f;
    }
    if (lane < F2) {
        float v = a1 * inv + __ldg(bias + 32 + lane);
        orow[32 + lane] = v > 0.f ? v : 0.f;
    }
}

// ---------------- edge_index passthrough tail ---------------
__global__ void ei_cast_k(const void* __restrict__ ei, float* __restrict__ o, long long cnt) {
    long long i = (long long)blockIdx.x * blockDim.x + threadIdx.x;
    if (i >= cnt) return;
    if (g_is64) o[i] = (float)((const long long*)ei)[i];
    else        o[i] = (float)((const int*)ei)[i];
}

extern "C" void kernel_launch(void* const* d_in, const int* in_sizes, int n_in,
                              void* d_out, int out_size) {
    const float* x    = (const float*)d_in[0];
    const void*  ei   = d_in[1];
    const float* W1   = (const float*)d_in[2];
    const float* as1w = (const float*)d_in[3];
    const float* ad1w = (const float*)d_in[4];
    const float* b1   = (const float*)d_in[5];
    const float* W2   = (const float*)d_in[6];
    const float* as2w = (const float*)d_in[7];
    const float* ad2w = (const float*)d_in[8];
    const float* b2   = (const float*)d_in[9];

    int       n  = in_sizes[0] / CIN;
    long long E  = (long long)in_sizes[1] / 2;
    long long ET = E + n;

    float *h1, *ho1, *h2, *pas1, *pad1, *pas2, *pad2;
    int *deg, *off, *cur, *csr, *part;
    cudaGetSymbolAddress((void**)&h1,  g_h1);
    cudaGetSymbolAddress((void**)&ho1, g_ho1);
    cudaGetSymbolAddress((void**)&h2,  g_h2);
    cudaGetSymbolAddress((void**)&pas1, g_as1);
    cudaGetSymbolAddress((void**)&pad1, g_ad1);
    cudaGetSymbolAddress((void**)&pas2, g_as2);
    cudaGetSymbolAddress((void**)&pad2, g_ad2);
    cudaGetSymbolAddress((void**)&deg, g_deg);
    cudaGetSymbolAddress((void**)&off, g_off);
    cudaGetSymbolAddress((void**)&cur, g_cur);
    cudaGetSymbolAddress((void**)&csr, g_csr);
    cudaGetSymbolAddress((void**)&part, g_part);

    int nodeBlocks = (n + 127) / 128;
    int edgeBlocks  = (int)((E + 255) / 256);
    int etBlocks    = (int)((ET + 255) / 256);
    int aggBlocks   = (n * 32 + 255) / 256;     // 8 warps (nodes) per block
    int scanBlocks  = (n + SCAN_CHUNK - 1) / SCAN_CHUNK;

    // ---------------- CSR build (shared by both layers) ----------------
    detect_k<<<1, 256>>>((const uint2*)ei, 2 * E);
    deginit_k<<<(n + 255) / 256, 256>>>(deg, n);
    count_k<<<edgeBlocks, 256>>>(ei, E, n, deg);
    blocksum_k<<<scanBlocks, 256>>>(deg, part, n);
    scan_partials_k<<<1, 1024>>>(part, scanBlocks);
    write_off_k<<<scanBlocks, 256>>>(deg, part, off, cur, n, (int)ET);
    scatter_k<<<etBlocks, 256>>>(ei, E, n, cur, csr);

    // ---------------- layer 1 ----------------
    gemm1_k<<<nodeBlocks, 128>>>(x, W1, as1w, ad1w, n, h1, pas1, pad1);
    agg_k<H1, H1P, H1P><<<aggBlocks, 256>>>(off, csr, pas1, pad1, h1, b1, n, ho1);

    // ---------------- layer 2 ----------------
    gemm2_k<<<nodeBlocks, 128>>>(ho1, W2, as2w, ad2w, n, h2, pas2, pad2);
    agg_k<H2, H2P, H2><<<aggBlocks, 256>>>(off, csr, pas2, pad2, h2, b2, n, (float*)d_out);

    // ---------------- optional edge_index passthrough tail ----------------
    long long nh2 = (long long)n * H2;
    long long tail = (long long)out_size - nh2;
    if (tail == 2 * E) {
        ei_cast_k<<<(int)((2 * E + 255) / 256), 256>>>(ei, (float*)d_out + nh2, 2 * E);
    } else if (tail == 4 * E) {
        cudaMemcpyAsync((char*)d_out + nh2 * sizeof(float), ei,
                        (size_t)(2 * E) * sizeof(long long), cudaMemcpyDeviceToDevice);
    }
}

// round 6
// speedup vs baseline: 2.2902x; 1.1926x over previous
#include <cuda_runtime.h>
#include <cuda_fp16.h>
#include <cstdint>

#define MAXN 100000
#define MAXE 3200000
#define CIN 128
#define H1 50
#define H1P 52            // fp32 row stride for ho1 (gemm2 input), 16B multiple
#define H2 40
#define NEG_SLOPE 0.2f
#define SCAN_CHUNK 1024
#define R1U 32            // layer1 h row: 32 uints = 64 fp16 = 128B (feat 0..24, as@25)
#define R2U 24            // layer2 h row: 24 uints = 48 fp16 =  96B (feat 0..19, as@20)

// -------- scratch (device globals; no runtime allocation allowed) ----------
__device__ unsigned g_h1u[(size_t)MAXN * R1U];  // fp16 h1 rows + embedded fp32 a_src
__device__ unsigned g_h2u[(size_t)MAXN * R2U];  // fp16 h2 rows + embedded fp32 a_src
__device__ float    g_ho1[(size_t)MAXN * H1P];  // agg1 output (fp32) -> gemm2 input
__device__ float    g_ad1[MAXN], g_ad2[MAXN];
__device__ int      g_deg[MAXN + 4];
__device__ int      g_off[MAXN + 1];
__device__ int      g_cur[MAXN];
__device__ int      g_part[1100];
__device__ int      g_csr[MAXE + MAXN];         // src indices grouped by dst
__device__ int      g_is64;

// ---------------- dtype probe ----------------
__global__ void detect_k(const uint2* __restrict__ ei8, long long twoE) {
    __shared__ int anyHi;
    if (threadIdx.x == 0) anyHi = 0;
    __syncthreads();
    long long K = twoE < 1024 ? twoE : 1024;
    for (long long i = threadIdx.x; i < K; i += blockDim.x) {
        uint2 v = ei8[i];
        if (v.y != 0u) anyHi = 1;
    }
    __syncthreads();
    if (threadIdx.x == 0) g_is64 = anyHi ? 0 : 1;
}

// ---------------- CSR build ----------------
__global__ void deginit_k(int* __restrict__ deg, int n) {
    int i = blockIdx.x * blockDim.x + threadIdx.x;
    if (i < n) deg[i] = 1;                      // self-loop
}

__global__ void count_k(const void* __restrict__ ei, long long E, int n, int* __restrict__ deg) {
    long long i = (long long)blockIdx.x * blockDim.x + threadIdx.x;
    if (i >= E) return;
    int d;
    if (g_is64) d = (int)((const long long*)ei)[E + i];
    else        d = ((const int*)ei)[E + i];
    if ((unsigned)d >= (unsigned)n) d = 0;
    atomicAdd(deg + d, 1);
}

__global__ void blocksum_k(const int* __restrict__ deg, int* __restrict__ part, int n) {
    __shared__ int sred[256];
    int base = blockIdx.x * SCAN_CHUNK;
    int t = threadIdx.x;
    int s = 0;
#pragma unroll
    for (int j = 0; j < SCAN_CHUNK / 256; j++) {
        int i = base + j * 256 + t;
        if (i < n) s += deg[i];
    }
    sred[t] = s;
    __syncthreads();
#pragma unroll
    for (int d = 128; d > 0; d >>= 1) {
        if (t < d) sred[t] += sred[t + d];
        __syncthreads();
    }
    if (t == 0) part[blockIdx.x] = sred[0];
}

__global__ void scan_partials_k(int* __restrict__ part, int B) {
    __shared__ int s[1024];
    int t = threadIdx.x;
    s[t] = (t < B) ? part[t] : 0;
    __syncthreads();
#pragma unroll
    for (int d = 1; d < 1024; d <<= 1) {
        int v = (t >= d) ? s[t - d] : 0;
        __syncthreads();
        s[t] += v;
        __syncthreads();
    }
    if (t < B) part[t] = t ? s[t - 1] : 0;
}

__global__ void write_off_k(const int* __restrict__ deg, const int* __restrict__ part,
                            int* __restrict__ off, int* __restrict__ cur,
                            int n, int total) {
    __shared__ int ts[256];
    int base = blockIdx.x * SCAN_CHUNK;
    int t = threadIdx.x;
    int i0 = base + t * 4;
    int v0 = 0, v1 = 0, v2 = 0, v3 = 0;
    if (i0 + 3 < n) {
        int4 q = *(const int4*)(deg + i0);
        v0 = q.x; v1 = q.y; v2 = q.z; v3 = q.w;
    } else {
        if (i0 + 0 < n) v0 = deg[i0 + 0];
        if (i0 + 1 < n) v1 = deg[i0 + 1];
        if (i0 + 2 < n) v2 = deg[i0 + 2];
        if (i0 + 3 < n) v3 = deg[i0 + 3];
    }
    ts[t] = v0 + v1 + v2 + v3;
    __syncthreads();
#pragma unroll
    for (int d = 1; d < 256; d <<= 1) {
        int v = (t >= d) ? ts[t - d] : 0;
        __syncthreads();
        ts[t] += v;
        __syncthreads();
    }
    int run = part[blockIdx.x] + (t ? ts[t - 1] : 0);
    if (i0 + 0 < n) { off[i0 + 0] = run; cur[i0 + 0] = run; run += v0; }
    if (i0 + 1 < n) { off[i0 + 1] = run; cur[i0 + 1] = run; run += v1; }
    if (i0 + 2 < n) { off[i0 + 2] = run; cur[i0 + 2] = run; run += v2; }
    if (i0 + 3 < n) { off[i0 + 3] = run; cur[i0 + 3] = run; run += v3; }
    if (blockIdx.x == 0 && t == 0) off[n] = total;
}

__global__ void scatter_k(const void* __restrict__ ei, long long E, int n,
                          int* __restrict__ cur, int* __restrict__ csr) {
    long long i = (long long)blockIdx.x * blockDim.x + threadIdx.x;
    long long ET = E + n;
    if (i >= ET) return;
    int s, d;
    if (i < E) {
        if (g_is64) {
            const long long* p = (const long long*)ei;
            s = (int)p[i]; d = (int)p[E + i];
        } else {
            const int* p = (const int*)ei;
            s = p[i]; d = p[E + i];
        }
        if ((unsigned)s >= (unsigned)n) s = 0;
        if ((unsigned)d >= (unsigned)n) d = 0;
    } else {
        s = d = (int)(i - E);
    }
    int pos = atomicAdd(cur + d, 1);
    csr[pos] = s;
}

// -------- f32x2 helpers (Blackwell packed fp32, PTX-only) --------
__device__ __forceinline__ unsigned long long splat2(float v) {
    unsigned long long r; unsigned b = __float_as_uint(v);
    asm("mov.b64 %0, {%1, %1};" : "=l"(r) : "r"(b));
    return r;
}
__device__ __forceinline__ void ffma2(unsigned long long& acc, unsigned long long a, unsigned long long b) {
    asm("fma.rn.f32x2 %0, %1, %2, %0;" : "+l"(acc) : "l"(a), "l"(b));
}
__device__ __forceinline__ float2 unpack2(unsigned long long v) {
    unsigned lo, hi;
    asm("mov.b64 {%0, %1}, %2;" : "=r"(lo), "=r"(hi) : "l"(v));
    return make_float2(__uint_as_float(lo), __uint_as_float(hi));
}

// ---------------- GEMM1: h1 = x @ W1 (128->50), fp16 rows + att dots --------
__global__ void gemm1_k(const float* __restrict__ x, const float* __restrict__ W,
                        const float* __restrict__ att_s, const float* __restrict__ att_d,
                        int n, unsigned* __restrict__ hrows, float* __restrict__ ad_o) {
    __shared__ float Ws[CIN * H1P];      // [k][f], stride 52 (8B-aligned rows)
    __shared__ float xs[128 * 17];
    __shared__ float sa[H1], sd[H1];
    int tid = threadIdx.x;
    for (int j = tid; j < CIN * H1; j += 128) {
        int k = j / H1, f = j - k * H1;
        Ws[k * H1P + f] = W[j];
    }
    if (tid < H1) { sa[tid] = att_s[tid]; sd[tid] = att_d[tid]; }

    int node = blockIdx.x * 128 + tid;
    unsigned long long acc2[25];
#pragma unroll
    for (int i = 0; i < 25; i++) acc2[i] = 0ull;

    const float4* x4 = (const float4*)x;
    for (int k0 = 0; k0 < CIN; k0 += 16) {
        __syncthreads();
#pragma unroll
        for (int j = tid; j < 512; j += 128) {
            int nd = j >> 2, c = j & 3;
            int gn = blockIdx.x * 128 + nd;
            float4 v = make_float4(0.f, 0.f, 0.f, 0.f);
            if (gn < n) v = x4[(size_t)gn * (CIN / 4) + (k0 >> 2) + c];
            float* p = &xs[nd * 17 + c * 4];
            p[0] = v.x; p[1] = v.y; p[2] = v.z; p[3] = v.w;
        }
        __syncthreads();
#pragma unroll
        for (int kk = 0; kk < 16; kk++) {
            unsigned long long xv2 = splat2(xs[tid * 17 + kk]);
            const unsigned long long* wr = (const unsigned long long*)&Ws[(k0 + kk) * H1P];
#pragma unroll
            for (int fp = 0; fp < 25; fp++) ffma2(acc2[fp], xv2, wr[fp]);
        }
    }
    if (node < n) {
        float s = 0.f, d = 0.f;
        unsigned* hr = hrows + (size_t)node * R1U;
#pragma unroll
        for (int fp = 0; fp < 25; fp++) {
            float2 v = unpack2(acc2[fp]);
            s += v.x * sa[2 * fp] + v.y * sa[2 * fp + 1];
            d += v.x * sd[2 * fp] + v.y * sd[2 * fp + 1];
            __half2 hh = __floats2half2_rn(v.x, v.y);
            hr[fp] = *(unsigned*)&hh;
        }
        hr[25] = __float_as_uint(s);            // embedded fp32 a_src
#pragma unroll
        for (int q = 26; q < R1U; q++) hr[q] = 0u;
        ad_o[node] = d;
    }
}

// ---------------- GEMM2: h2 = ho1 @ W2 (50->40), fp16 rows + att dots -------
__global__ void gemm2_k(const float* __restrict__ hin /*stride H1P*/, const float* __restrict__ W,
                        const float* __restrict__ att_s, const float* __restrict__ att_d,
                        int n, unsigned* __restrict__ hrows, float* __restrict__ ad_o) {
#define H2P 44
    __shared__ float Ws[H1 * H2P];       // stride 44 (8B-aligned rows)
    __shared__ float xs[128 * 53];
    __shared__ float sa[H2], sd[H2];
    int tid = threadIdx.x;
    for (int j = tid; j < H1 * H2; j += 128) {
        int k = j / H2, f = j - k * H2;
        Ws[k * H2P + f] = W[j];
    }
    if (tid < H2) { sa[tid] = att_s[tid]; sd[tid] = att_d[tid]; }

    const float4* hin4 = (const float4*)hin;
#pragma unroll
    for (int j = tid; j < 128 * 13; j += 128) {
        int nd = j / 13, q = j - nd * 13;
        int gn = blockIdx.x * 128 + nd;
        float4 v = make_float4(0.f, 0.f, 0.f, 0.f);
        if (gn < n) v = hin4[(size_t)gn * 13 + q];
        float* p = &xs[nd * 53 + q * 4];
        p[0] = v.x; p[1] = v.y; p[2] = v.z; p[3] = v.w;
    }
    __syncthreads();

    int node = blockIdx.x * 128 + tid;
    unsigned long long acc2[20];
#pragma unroll
    for (int i = 0; i < 20; i++) acc2[i] = 0ull;
#pragma unroll 2
    for (int k = 0; k < H1; k++) {
        unsigned long long xv2 = splat2(xs[tid * 53 + k]);
        const unsigned long long* wr = (const unsigned long long*)&Ws[k * H2P];
#pragma unroll
        for (int fp = 0; fp < 20; fp++) ffma2(acc2[fp], xv2, wr[fp]);
    }
    if (node < n) {
        float s = 0.f, d = 0.f;
        unsigned* hr = hrows + (size_t)node * R2U;
#pragma unroll
        for (int fp = 0; fp < 20; fp++) {
            float2 v = unpack2(acc2[fp]);
            s += v.x * sa[2 * fp] + v.y * sa[2 * fp + 1];
            d += v.x * sd[2 * fp] + v.y * sd[2 * fp + 1];
            __half2 hh = __floats2half2_rn(v.x, v.y);
            hr[fp] = *(unsigned*)&hh;
        }
        hr[20] = __float_as_uint(s);
        hr[21] = 0u; hr[22] = 0u; hr[23] = 0u;
        ad_o[node] = d;
    }
}

// ---------------- fused GAT aggregation: one warp per dst node ---------------
// h rows are fp16 with fp32 a_src bits embedded at uint slot AS_LANE.
// Each lane loads ONE uint of the row (2 features); a_src broadcast via shfl.
template <int NF2, int STRIDE_U, int AS_LANE, int SOUT>
__global__ void agg_k(const int* __restrict__ off, const int* __restrict__ csr,
                      const float* __restrict__ ad, const unsigned* __restrict__ hrows,
                      const float* __restrict__ bias, int n, float* __restrict__ out) {
    int warp = (blockIdx.x * blockDim.x + threadIdx.x) >> 5;
    int lane = threadIdx.x & 31;
    if (warp >= n) return;

    int beg = __ldg(off + warp), end = __ldg(off + warp + 1);
    float adv = __ldg(ad + warp);
    float ax = 0.f, ay = 0.f, z = 0.f;
    bool ldok = (STRIDE_U == 32) || (lane < STRIDE_U);

    int p = beg;
    for (; p + 8 <= end; p += 8) {
        int s[8]; unsigned r[8];
#pragma unroll
        for (int u = 0; u < 8; u++) s[u] = __ldg(csr + p + u);
#pragma unroll
        for (int u = 0; u < 8; u++)
            r[u] = ldok ? __ldg(hrows + (size_t)s[u] * STRIDE_U + lane) : 0u;
#pragma unroll
        for (int u = 0; u < 8; u++) {
            float asv = __shfl_sync(0xffffffffu, __uint_as_float(r[u]), AS_LANE);
            float e = asv + adv;
            e = e > 0.f ? e : NEG_SLOPE * e;
            float w = __expf(e);
            float2 hv = __half22float2(*(__half2*)&r[u]);
            z += w; ax += w * hv.x; ay += w * hv.y;
        }
    }
    for (; p < end; p++) {
        int s = __ldg(csr + p);
        unsigned r = ldok ? __ldg(hrows + (size_t)s * STRIDE_U + lane) : 0u;
        float asv = __shfl_sync(0xffffffffu, __uint_as_float(r), AS_LANE);
        float e = asv + adv;
        e = e > 0.f ? e : NEG_SLOPE * e;
        float w = __expf(e);
        float2 hv = __half22float2(*(__half2*)&r);
        z += w; ax += w * hv.x; ay += w * hv.y;
    }

    float inv = 1.f / z;                        // z >= exp(self-loop) > 0
    if (lane < NF2) {
        float2 b = __ldg((const float2*)bias + lane);
        float vx = ax * inv + b.x;
        float vy = ay * inv + b.y;
        float2 o;
        o.x = vx > 0.f ? vx : 0.f;
        o.y = vy > 0.f ? vy : 0.f;
        *(float2*)(out + (size_t)warp * SOUT + 2 * lane) = o;
    }
}

// ---------------- edge_index passthrough tail ---------------
__global__ void ei_cast_k(const void* __restrict__ ei, float* __restrict__ o, long long cnt) {
    long long i = (long long)blockIdx.x * blockDim.x + threadIdx.x;
    if (i >= cnt) return;
    if (g_is64) o[i] = (float)((const long long*)ei)[i];
    else        o[i] = (float)((const int*)ei)[i];
}

extern "C" void kernel_launch(void* const* d_in, const int* in_sizes, int n_in,
                              void* d_out, int out_size) {
    const float* x    = (const float*)d_in[0];
    const void*  ei   = d_in[1];
    const float* W1   = (const float*)d_in[2];
    const float* as1w = (const float*)d_in[3];
    const float* ad1w = (const float*)d_in[4];
    const float* b1   = (const float*)d_in[5];
    const float* W2   = (const float*)d_in[6];
    const float* as2w = (const float*)d_in[7];
    const float* ad2w = (const float*)d_in[8];
    const float* b2   = (const float*)d_in[9];

    int       n  = in_sizes[0] / CIN;
    long long E  = (long long)in_sizes[1] / 2;
    long long ET = E + n;

    unsigned *h1u, *h2u;
    float *ho1, *pad1, *pad2;
    int *deg, *off, *cur, *csr, *part;
    cudaGetSymbolAddress((void**)&h1u, g_h1u);
    cudaGetSymbolAddress((void**)&h2u, g_h2u);
    cudaGetSymbolAddress((void**)&ho1, g_ho1);
    cudaGetSymbolAddress((void**)&pad1, g_ad1);
    cudaGetSymbolAddress((void**)&pad2, g_ad2);
    cudaGetSymbolAddress((void**)&deg, g_deg);
    cudaGetSymbolAddress((void**)&off, g_off);
    cudaGetSymbolAddress((void**)&cur, g_cur);
    cudaGetSymbolAddress((void**)&csr, g_csr);
    cudaGetSymbolAddress((void**)&part, g_part);

    int nodeBlocks = (n + 127) / 128;
    int edgeBlocks  = (int)((E + 255) / 256);
    int etBlocks    = (int)((ET + 255) / 256);
    int aggBlocks   = (n * 32 + 255) / 256;
    int scanBlocks  = (n + SCAN_CHUNK - 1) / SCAN_CHUNK;

    // ---------------- CSR build (shared by both layers) ----------------
    detect_k<<<1, 256>>>((const uint2*)ei, 2 * E);
    deginit_k<<<(n + 255) / 256, 256>>>(deg, n);
    count_k<<<edgeBlocks, 256>>>(ei, E, n, deg);
    blocksum_k<<<scanBlocks, 256>>>(deg, part, n);
    scan_partials_k<<<1, 1024>>>(part, scanBlocks);
    write_off_k<<<scanBlocks, 256>>>(deg, part, off, cur, n, (int)ET);
    scatter_k<<<etBlocks, 256>>>(ei, E, n, cur, csr);

    // ---------------- layer 1 ----------------
    gemm1_k<<<nodeBlocks, 128>>>(x, W1, as1w, ad1w, n, h1u, pad1);
    agg_k<25, R1U, 25, H1P><<<aggBlocks, 256>>>(off, csr, pad1, h1u, b1, n, ho1);

    // ---------------- layer 2 ----------------
    gemm2_k<<<nodeBlocks, 128>>>(ho1, W2, as2w, ad2w, n, h2u, pad2);
    agg_k<20, R2U, 20, H2><<<aggBlocks, 256>>>(off, csr, pad2, h2u, b2, n, (float*)d_out);

    // ---------------- optional edge_index passthrough tail ----------------
    long long nh2 = (long long)n * H2;
    long long tail = (long long)out_size - nh2;
    if (tail == 2 * E) {
        ei_cast_k<<<(int)((2 * E + 255) / 256), 256>>>(ei, (float*)d_out + nh2, 2 * E);
    } else if (tail == 4 * E) {
        cudaMemcpyAsync((char*)d_out + nh2 * sizeof(float), ei,
                        (size_t)(2 * E) * sizeof(long long), cudaMemcpyDeviceToDevice);
    }
}